// round 1
// baseline (speedup 1.0000x reference)
#include <cuda_runtime.h>
#include <math.h>

// Problem constants
#define Bc 2
#define Lc 2048
#define Sc 2048
#define Dc 1024
#define Hc 16
#define NSc 8
#define NSLOTc 512
#define HDc 64

// ---------------- scratch (device globals; no allocation allowed) ----------------
__device__ float g_mem[NSLOTc * Dc];                 // ln_kv(E_slots)
__device__ float g_ek[NSLOTc * Dc];                  // mem @ Wk^T
__device__ float g_ev[NSLOTc * Dc];                  // mem @ Wv^T
__device__ float g_gkv[Sc * Dc];                     // silu(c_kv @ Wpe^T)
__device__ float g_K[(size_t)Bc * Sc * Dc];          // gathered+gated K
__device__ float g_V[(size_t)Bc * Sc * Dc];          // gathered+gated V
__device__ float g_xh[(size_t)Bc * Lc * Dc];         // ln_q(x_q * gate_q)
__device__ float g_Q[(size_t)Bc * Lc * Dc];          // xh @ Wq^T
__device__ float g_ao[(size_t)Bc * Lc * Dc];         // attention output

// ---------------- block reduce helper ----------------
__device__ __forceinline__ float blockReduceSum(float v, float* red) {
    int tid = threadIdx.x;
    int lane = tid & 31, w = tid >> 5;
#pragma unroll
    for (int o = 16; o; o >>= 1) v += __shfl_xor_sync(0xffffffffu, v, o);
    if (lane == 0) red[w] = v;
    __syncthreads();
    if (tid == 0) {
        float s = 0.f;
#pragma unroll
        for (int i = 0; i < 8; i++) s += red[i];
        red[0] = s;
    }
    __syncthreads();
    float r = red[0];
    __syncthreads();
    return r;
}

// ---------------- 1) layernorm rows (E_slots -> g_mem) ----------------
__global__ void ln_rows_kernel(const float* __restrict__ X, const float* __restrict__ gw,
                               const float* __restrict__ bw, float* __restrict__ Y) {
    __shared__ float red[8];
    int r = blockIdx.x, tid = threadIdx.x;
    const float* xr = X + (size_t)r * Dc;
    float4 x = *(const float4*)(xr + tid * 4);
    float mean = blockReduceSum(x.x + x.y + x.z + x.w, red) * (1.0f / Dc);
    float d0 = x.x - mean, d1 = x.y - mean, d2 = x.z - mean, d3 = x.w - mean;
    float var = blockReduceSum(d0 * d0 + d1 * d1 + d2 * d2 + d3 * d3, red) * (1.0f / Dc);
    float rs = rsqrtf(var + 1e-5f);
    float4 g4 = *(const float4*)(gw + tid * 4);
    float4 b4 = *(const float4*)(bw + tid * 4);
    float4 y = make_float4(d0 * rs * g4.x + b4.x, d1 * rs * g4.y + b4.y,
                           d2 * rs * g4.z + b4.z, d3 * rs * g4.w + b4.w);
    *(float4*)(Y + (size_t)r * Dc + tid * 4) = y;
}

// ---------------- 2) gate_kv[s,d] = silu( sum_m rho_m^(S-1-s) * Wpe[d,m] ) ----------------
__global__ void gatekv_kernel(const float* __restrict__ rhos, const float* __restrict__ Wpe) {
    __shared__ float c[NSc];
    int s = blockIdx.x, tid = threadIdx.x;
    if (tid < NSc) {
        double age = (double)(Sc - 1 - s);
        c[tid] = (float)exp(age * log((double)rhos[tid]));
    }
    __syncthreads();
    float cc[NSc];
#pragma unroll
    for (int m = 0; m < NSc; m++) cc[m] = c[m];
    float out[4];
#pragma unroll
    for (int e = 0; e < 4; e++) {
        int d = tid * 4 + e;
        const float* w = Wpe + (size_t)d * NSc;
        float t = 0.f;
#pragma unroll
        for (int m = 0; m < NSc; m++) t += cc[m] * w[m];
        out[e] = t / (1.0f + __expf(-t));
    }
    *(float4*)(g_gkv + (size_t)s * Dc + tid * 4) = make_float4(out[0], out[1], out[2], out[3]);
}

// ---------------- 3) gather + gate: K/V[b,s,:] = E{k,v}[idx]*gate_kv[s] ----------------
__global__ void gather_kernel(const int* __restrict__ xidx) {
    int bs = blockIdx.x, tid = threadIdx.x;
    int s = bs & (Sc - 1);
    int idx = xidx[bs];
    const float4* ek = (const float4*)g_ek + (size_t)idx * (Dc / 4);
    const float4* ev = (const float4*)g_ev + (size_t)idx * (Dc / 4);
    const float4* gk = (const float4*)g_gkv + (size_t)s * (Dc / 4);
    float4 w = gk[tid];
    float4 a = ek[tid];
    float4 b = ev[tid];
    float4* K4 = (float4*)g_K + (size_t)bs * (Dc / 4);
    float4* V4 = (float4*)g_V + (size_t)bs * (Dc / 4);
    K4[tid] = make_float4(a.x * w.x, a.y * w.y, a.z * w.z, a.w * w.w);
    V4[tid] = make_float4(b.x * w.x, b.y * w.y, b.z * w.z, b.w * w.w);
}

// ---------------- 4) xh = ln_q( x_q * silu(C_seq @ Wpe^T) ) ----------------
__global__ void gateq_ln_kernel(const float* __restrict__ xq, const float* __restrict__ Cs,
                                const float* __restrict__ Wpe,
                                const float* __restrict__ gw, const float* __restrict__ bw) {
    __shared__ float red[8];
    __shared__ float c[NSc];
    int r = blockIdx.x, tid = threadIdx.x;
    if (tid < NSc) c[tid] = Cs[(size_t)r * NSc + tid];
    __syncthreads();
    float cc[NSc];
#pragma unroll
    for (int m = 0; m < NSc; m++) cc[m] = c[m];
    float4 x = *(const float4*)(xq + (size_t)r * Dc + tid * 4);
    float xv[4] = {x.x, x.y, x.z, x.w};
    float y[4];
#pragma unroll
    for (int e = 0; e < 4; e++) {
        int d = tid * 4 + e;
        const float* w = Wpe + (size_t)d * NSc;
        float t = 0.f;
#pragma unroll
        for (int m = 0; m < NSc; m++) t += cc[m] * w[m];
        y[e] = xv[e] * (t / (1.0f + __expf(-t)));
    }
    float mean = blockReduceSum(y[0] + y[1] + y[2] + y[3], red) * (1.0f / Dc);
#pragma unroll
    for (int e = 0; e < 4; e++) y[e] -= mean;
    float var = blockReduceSum(y[0] * y[0] + y[1] * y[1] + y[2] * y[2] + y[3] * y[3], red) * (1.0f / Dc);
    float rs = rsqrtf(var + 1e-5f);
    float4 g4 = *(const float4*)(gw + tid * 4);
    float4 b4 = *(const float4*)(bw + tid * 4);
    float4 o = make_float4(y[0] * rs * g4.x + b4.x, y[1] * rs * g4.y + b4.y,
                           y[2] * rs * g4.z + b4.z, y[3] * rs * g4.w + b4.w);
    *(float4*)(g_xh + (size_t)r * Dc + tid * 4) = o;
}

// ---------------- 5) GEMM: C[M,N] = A[M,K] * B[N,K]^T, all row-major, dims %64/%16 ----------------
__global__ void gemm_abt_kernel(const float* __restrict__ A, const float* __restrict__ Bm,
                                float* __restrict__ C, int M, int N, int K) {
    __shared__ float As[16][68];
    __shared__ float Bs[16][68];
    int tid = threadIdx.x;
    int ty = tid >> 4, tx = tid & 15;
    int row0 = blockIdx.y * 64, col0 = blockIdx.x * 64;
    int lr = tid >> 2;
    int lk = (tid & 3) * 4;
    const float* Ap = A + (size_t)(row0 + lr) * K + lk;
    const float* Bp = Bm + (size_t)(col0 + lr) * K + lk;
    float acc[4][4] = {};
    for (int k0 = 0; k0 < K; k0 += 16) {
        float4 av = *(const float4*)(Ap + k0);
        float4 bv = *(const float4*)(Bp + k0);
        As[lk + 0][lr] = av.x; As[lk + 1][lr] = av.y; As[lk + 2][lr] = av.z; As[lk + 3][lr] = av.w;
        Bs[lk + 0][lr] = bv.x; Bs[lk + 1][lr] = bv.y; Bs[lk + 2][lr] = bv.z; Bs[lk + 3][lr] = bv.w;
        __syncthreads();
#pragma unroll
        for (int kk = 0; kk < 16; kk++) {
            float4 a = *(const float4*)&As[kk][ty * 4];
            float4 b = *(const float4*)&Bs[kk][tx * 4];
            acc[0][0] += a.x * b.x; acc[0][1] += a.x * b.y; acc[0][2] += a.x * b.z; acc[0][3] += a.x * b.w;
            acc[1][0] += a.y * b.x; acc[1][1] += a.y * b.y; acc[1][2] += a.y * b.z; acc[1][3] += a.y * b.w;
            acc[2][0] += a.z * b.x; acc[2][1] += a.z * b.y; acc[2][2] += a.z * b.z; acc[2][3] += a.z * b.w;
            acc[3][0] += a.w * b.x; acc[3][1] += a.w * b.y; acc[3][2] += a.w * b.z; acc[3][3] += a.w * b.w;
        }
        __syncthreads();
    }
#pragma unroll
    for (int i = 0; i < 4; i++) {
        *(float4*)(C + (size_t)(row0 + ty * 4 + i) * N + col0 + tx * 4) =
            make_float4(acc[i][0], acc[i][1], acc[i][2], acc[i][3]);
    }
}

// ---------------- 6) flash attention: 64-query x 64-key tiles, HD=64 ----------------
#define AW 68
__global__ void attn_kernel() {
    extern __shared__ float sm[];
    float* Qst = sm;                 // [64 d][AW]  (d-major, transposed Q tile)
    float* KP  = sm + 64 * AW;       // K tile d-major, then reused as P [key][AW]
    float* Vs  = sm + 2 * 64 * AW;   // [64 s][64 d] natural
    int b = blockIdx.y >> 4, h = blockIdx.y & 15;
    int q0 = blockIdx.x * 64;
    int tid = threadIdx.x, ty = tid >> 4, tx = tid & 15;
    int lr = tid >> 2;
    int lc = (tid & 3) * 16;
    const float* Qb = g_Q + ((size_t)b * Lc + q0) * Dc + h * HDc;
    const float* Kb = g_K + (size_t)b * Sc * Dc + h * HDc;
    const float* Vb = g_V + (size_t)b * Sc * Dc + h * HDc;
#pragma unroll
    for (int j = 0; j < 4; j++) {
        int d = lc + j * 4;
        float4 v = *(const float4*)(Qb + (size_t)lr * Dc + d);
        Qst[(d + 0) * AW + lr] = v.x; Qst[(d + 1) * AW + lr] = v.y;
        Qst[(d + 2) * AW + lr] = v.z; Qst[(d + 3) * AW + lr] = v.w;
    }
    float m[4], l[4], o[4][4];
#pragma unroll
    for (int i = 0; i < 4; i++) {
        m[i] = -1e30f; l[i] = 0.f;
#pragma unroll
        for (int j = 0; j < 4; j++) o[i][j] = 0.f;
    }
    for (int s0 = 0; s0 < Sc; s0 += 64) {
        __syncthreads();
#pragma unroll
        for (int j = 0; j < 4; j++) {
            int d = lc + j * 4;
            float4 kv = *(const float4*)(Kb + (size_t)(s0 + lr) * Dc + d);
            KP[(d + 0) * AW + lr] = kv.x; KP[(d + 1) * AW + lr] = kv.y;
            KP[(d + 2) * AW + lr] = kv.z; KP[(d + 3) * AW + lr] = kv.w;
            float4 vv = *(const float4*)(Vb + (size_t)(s0 + lr) * Dc + d);
            *(float4*)(Vs + lr * 64 + d) = vv;
        }
        __syncthreads();
        float p[4][4] = {};
#pragma unroll 16
        for (int d = 0; d < 64; d++) {
            float4 a = *(const float4*)(Qst + d * AW + ty * 4);
            float4 bb = *(const float4*)(KP + d * AW + tx * 4);
            p[0][0] += a.x * bb.x; p[0][1] += a.x * bb.y; p[0][2] += a.x * bb.z; p[0][3] += a.x * bb.w;
            p[1][0] += a.y * bb.x; p[1][1] += a.y * bb.y; p[1][2] += a.y * bb.z; p[1][3] += a.y * bb.w;
            p[2][0] += a.z * bb.x; p[2][1] += a.z * bb.y; p[2][2] += a.z * bb.z; p[2][3] += a.z * bb.w;
            p[3][0] += a.w * bb.x; p[3][1] += a.w * bb.y; p[3][2] += a.w * bb.z; p[3][3] += a.w * bb.w;
        }
#pragma unroll
        for (int i = 0; i < 4; i++) {
#pragma unroll
            for (int j = 0; j < 4; j++) p[i][j] *= 0.125f;  // 1/sqrt(64)
            float rmax = fmaxf(fmaxf(p[i][0], p[i][1]), fmaxf(p[i][2], p[i][3]));
#pragma unroll
            for (int off = 1; off < 16; off <<= 1)
                rmax = fmaxf(rmax, __shfl_xor_sync(0xffffffffu, rmax, off));
            float mn = fmaxf(m[i], rmax);
            float al = __expf(m[i] - mn);
            float rs = 0.f;
#pragma unroll
            for (int j = 0; j < 4; j++) { p[i][j] = __expf(p[i][j] - mn); rs += p[i][j]; }
#pragma unroll
            for (int off = 1; off < 16; off <<= 1)
                rs += __shfl_xor_sync(0xffffffffu, rs, off);
            l[i] = l[i] * al + rs;
            m[i] = mn;
#pragma unroll
            for (int j = 0; j < 4; j++) o[i][j] *= al;
        }
        __syncthreads();
#pragma unroll
        for (int j = 0; j < 4; j++)
#pragma unroll
            for (int i = 0; i < 4; i++)
                KP[(tx * 4 + j) * AW + ty * 4 + i] = p[i][j];
        __syncthreads();
#pragma unroll 16
        for (int kk = 0; kk < 64; kk++) {
            float4 a = *(const float4*)(KP + kk * AW + ty * 4);
            float4 bb = *(const float4*)(Vs + kk * 64 + tx * 4);
            o[0][0] += a.x * bb.x; o[0][1] += a.x * bb.y; o[0][2] += a.x * bb.z; o[0][3] += a.x * bb.w;
            o[1][0] += a.y * bb.x; o[1][1] += a.y * bb.y; o[1][2] += a.y * bb.z; o[1][3] += a.y * bb.w;
            o[2][0] += a.z * bb.x; o[2][1] += a.z * bb.y; o[2][2] += a.z * bb.z; o[2][3] += a.z * bb.w;
            o[3][0] += a.w * bb.x; o[3][1] += a.w * bb.y; o[3][2] += a.w * bb.z; o[3][3] += a.w * bb.w;
        }
    }
    float* Ob = g_ao + ((size_t)b * Lc + q0) * Dc + h * HDc;
#pragma unroll
    for (int i = 0; i < 4; i++) {
        float inv = 1.0f / l[i];
        *(float4*)(Ob + (size_t)(ty * 4 + i) * Dc + tx * 4) =
            make_float4(o[i][0] * inv, o[i][1] * inv, o[i][2] * inv, o[i][3] * inv);
    }
}

// ---------------- launch ----------------
extern "C" void kernel_launch(void* const* d_in, const int* in_sizes, int n_in,
                              void* d_out, int out_size) {
    const float* x_q  = (const float*)d_in[0];
    const int*   xidx = (const int*)d_in[1];
    const float* E    = (const float*)d_in[2];
    const float* rhos = (const float*)d_in[3];
    const float* Cs   = (const float*)d_in[4];
    const float* Wq   = (const float*)d_in[5];
    const float* Wk   = (const float*)d_in[6];
    const float* Wv   = (const float*)d_in[7];
    const float* Wo   = (const float*)d_in[8];
    const float* Wpe  = (const float*)d_in[9];
    const float* lnkg = (const float*)d_in[10];
    const float* lnkb = (const float*)d_in[11];
    const float* lnqg = (const float*)d_in[12];
    const float* lnqb = (const float*)d_in[13];
    float* out = (float*)d_out;

    float *p_mem, *p_ek, *p_ev, *p_xh, *p_Q, *p_ao;
    cudaGetSymbolAddress((void**)&p_mem, g_mem);
    cudaGetSymbolAddress((void**)&p_ek, g_ek);
    cudaGetSymbolAddress((void**)&p_ev, g_ev);
    cudaGetSymbolAddress((void**)&p_xh, g_xh);
    cudaGetSymbolAddress((void**)&p_Q, g_Q);
    cudaGetSymbolAddress((void**)&p_ao, g_ao);

    // KV side
    ln_rows_kernel<<<NSLOTc, 256>>>(E, lnkg, lnkb, p_mem);
    gemm_abt_kernel<<<dim3(Dc / 64, NSLOTc / 64), 256>>>(p_mem, Wk, p_ek, NSLOTc, Dc, Dc);
    gemm_abt_kernel<<<dim3(Dc / 64, NSLOTc / 64), 256>>>(p_mem, Wv, p_ev, NSLOTc, Dc, Dc);
    gatekv_kernel<<<Sc, 256>>>(rhos, Wpe);
    gather_kernel<<<Bc * Sc, 256>>>(xidx);

    // Q side
    gateq_ln_kernel<<<Bc * Lc, 256>>>(x_q, Cs, Wpe, lnqg, lnqb);
    gemm_abt_kernel<<<dim3(Dc / 64, (Bc * Lc) / 64), 256>>>(p_xh, Wq, p_Q, Bc * Lc, Dc, Dc);

    // Attention
    const int attn_smem = (2 * 64 * AW + 64 * 64) * (int)sizeof(float);  // 51200 B
    cudaFuncSetAttribute(attn_kernel, cudaFuncAttributeMaxDynamicSharedMemorySize, attn_smem);
    attn_kernel<<<dim3(Lc / 64, Bc * Hc), 256, attn_smem>>>();

    // Output projection
    gemm_abt_kernel<<<dim3(Dc / 64, (Bc * Lc) / 64), 256>>>(p_ao, Wo, out, Bc * Lc, Dc, Dc);
}

// round 2
// speedup vs baseline: 1.0007x; 1.0007x over previous
#include <cuda_runtime.h>
#include <math.h>

// Problem constants
#define Bc 2
#define Lc 2048
#define Sc 2048
#define Dc 1024
#define Hc 16
#define NSc 8
#define NSLOTc 512
#define HDc 64

// ---------------- scratch (device globals; no allocation allowed) ----------------
__device__ float g_mem[NSLOTc * Dc];                 // ln_kv(E_slots)
__device__ float g_ek[NSLOTc * Dc];                  // mem @ Wk^T
__device__ float g_ev[NSLOTc * Dc];                  // mem @ Wv^T
__device__ float g_gkv[Sc * Dc];                     // silu(c_kv @ Wpe^T)
__device__ float g_K[(size_t)Bc * Sc * Dc];          // gathered+gated K
__device__ float g_V[(size_t)Bc * Sc * Dc];          // gathered+gated V
__device__ float g_xh[(size_t)Bc * Lc * Dc];         // ln_q(x_q * gate_q)
__device__ float g_Q[(size_t)Bc * Lc * Dc];          // xh @ Wq^T
__device__ float g_ao[(size_t)Bc * Lc * Dc];         // attention output

// ---------------- block reduce helper ----------------
__device__ __forceinline__ float blockReduceSum(float v, float* red) {
    int tid = threadIdx.x;
    int lane = tid & 31, w = tid >> 5;
#pragma unroll
    for (int o = 16; o; o >>= 1) v += __shfl_xor_sync(0xffffffffu, v, o);
    if (lane == 0) red[w] = v;
    __syncthreads();
    if (tid == 0) {
        float s = 0.f;
#pragma unroll
        for (int i = 0; i < 8; i++) s += red[i];
        red[0] = s;
    }
    __syncthreads();
    float r = red[0];
    __syncthreads();
    return r;
}

// ---------------- 1) layernorm rows (E_slots -> g_mem) ----------------
__global__ void ln_rows_kernel(const float* __restrict__ X, const float* __restrict__ gw,
                               const float* __restrict__ bw, float* __restrict__ Y) {
    __shared__ float red[8];
    int r = blockIdx.x, tid = threadIdx.x;
    const float* xr = X + (size_t)r * Dc;
    float4 x = *(const float4*)(xr + tid * 4);
    float mean = blockReduceSum(x.x + x.y + x.z + x.w, red) * (1.0f / Dc);
    float d0 = x.x - mean, d1 = x.y - mean, d2 = x.z - mean, d3 = x.w - mean;
    float var = blockReduceSum(d0 * d0 + d1 * d1 + d2 * d2 + d3 * d3, red) * (1.0f / Dc);
    float rs = rsqrtf(var + 1e-5f);
    float4 g4 = *(const float4*)(gw + tid * 4);
    float4 b4 = *(const float4*)(bw + tid * 4);
    float4 y = make_float4(d0 * rs * g4.x + b4.x, d1 * rs * g4.y + b4.y,
                           d2 * rs * g4.z + b4.z, d3 * rs * g4.w + b4.w);
    *(float4*)(Y + (size_t)r * Dc + tid * 4) = y;
}

// ---------------- 2) gate_kv[s,d] = silu( sum_m rho_m^(S-1-s) * Wpe[d,m] ) ----------------
__global__ void gatekv_kernel(const float* __restrict__ rhos, const float* __restrict__ Wpe) {
    __shared__ float c[NSc];
    int s = blockIdx.x, tid = threadIdx.x;
    if (tid < NSc) {
        double age = (double)(Sc - 1 - s);
        c[tid] = (float)exp(age * log((double)rhos[tid]));
    }
    __syncthreads();
    float cc[NSc];
#pragma unroll
    for (int m = 0; m < NSc; m++) cc[m] = c[m];
    float out[4];
#pragma unroll
    for (int e = 0; e < 4; e++) {
        int d = tid * 4 + e;
        const float* w = Wpe + (size_t)d * NSc;
        float t = 0.f;
#pragma unroll
        for (int m = 0; m < NSc; m++) t += cc[m] * w[m];
        out[e] = t / (1.0f + __expf(-t));
    }
    *(float4*)(g_gkv + (size_t)s * Dc + tid * 4) = make_float4(out[0], out[1], out[2], out[3]);
}

// ---------------- 3) gather + gate: K/V[b,s,:] = E{k,v}[idx]*gate_kv[s] ----------------
__global__ void gather_kernel(const int* __restrict__ xidx) {
    int bs = blockIdx.x, tid = threadIdx.x;
    int s = bs & (Sc - 1);
    int idx = xidx[bs];
    const float4* ek = (const float4*)g_ek + (size_t)idx * (Dc / 4);
    const float4* ev = (const float4*)g_ev + (size_t)idx * (Dc / 4);
    const float4* gk = (const float4*)g_gkv + (size_t)s * (Dc / 4);
    float4 w = gk[tid];
    float4 a = ek[tid];
    float4 b = ev[tid];
    float4* K4 = (float4*)g_K + (size_t)bs * (Dc / 4);
    float4* V4 = (float4*)g_V + (size_t)bs * (Dc / 4);
    K4[tid] = make_float4(a.x * w.x, a.y * w.y, a.z * w.z, a.w * w.w);
    V4[tid] = make_float4(b.x * w.x, b.y * w.y, b.z * w.z, b.w * w.w);
}

// ---------------- 4) xh = ln_q( x_q * silu(C_seq @ Wpe^T) ) ----------------
__global__ void gateq_ln_kernel(const float* __restrict__ xq, const float* __restrict__ Cs,
                                const float* __restrict__ Wpe,
                                const float* __restrict__ gw, const float* __restrict__ bw) {
    __shared__ float red[8];
    __shared__ float c[NSc];
    int r = blockIdx.x, tid = threadIdx.x;
    if (tid < NSc) c[tid] = Cs[(size_t)r * NSc + tid];
    __syncthreads();
    float cc[NSc];
#pragma unroll
    for (int m = 0; m < NSc; m++) cc[m] = c[m];
    float4 x = *(const float4*)(xq + (size_t)r * Dc + tid * 4);
    float xv[4] = {x.x, x.y, x.z, x.w};
    float y[4];
#pragma unroll
    for (int e = 0; e < 4; e++) {
        int d = tid * 4 + e;
        const float* w = Wpe + (size_t)d * NSc;
        float t = 0.f;
#pragma unroll
        for (int m = 0; m < NSc; m++) t += cc[m] * w[m];
        y[e] = xv[e] * (t / (1.0f + __expf(-t)));
    }
    float mean = blockReduceSum(y[0] + y[1] + y[2] + y[3], red) * (1.0f / Dc);
#pragma unroll
    for (int e = 0; e < 4; e++) y[e] -= mean;
    float var = blockReduceSum(y[0] * y[0] + y[1] * y[1] + y[2] * y[2] + y[3] * y[3], red) * (1.0f / Dc);
    float rs = rsqrtf(var + 1e-5f);
    float4 g4 = *(const float4*)(gw + tid * 4);
    float4 b4 = *(const float4*)(bw + tid * 4);
    float4 o = make_float4(y[0] * rs * g4.x + b4.x, y[1] * rs * g4.y + b4.y,
                           y[2] * rs * g4.z + b4.z, y[3] * rs * g4.w + b4.w);
    *(float4*)(g_xh + (size_t)r * Dc + tid * 4) = o;
}

// ---------------- 5) GEMM: C[M,N] = A[M,K] * B[N,K]^T, all row-major, dims %64/%16 ----------------
__global__ void gemm_abt_kernel(const float* __restrict__ A, const float* __restrict__ Bm,
                                float* __restrict__ C, int M, int N, int K) {
    __shared__ float As[16][68];
    __shared__ float Bs[16][68];
    int tid = threadIdx.x;
    int ty = tid >> 4, tx = tid & 15;
    int row0 = blockIdx.y * 64, col0 = blockIdx.x * 64;
    int lr = tid >> 2;
    int lk = (tid & 3) * 4;
    const float* Ap = A + (size_t)(row0 + lr) * K + lk;
    const float* Bp = Bm + (size_t)(col0 + lr) * K + lk;
    float acc[4][4] = {};
    for (int k0 = 0; k0 < K; k0 += 16) {
        float4 av = *(const float4*)(Ap + k0);
        float4 bv = *(const float4*)(Bp + k0);
        As[lk + 0][lr] = av.x; As[lk + 1][lr] = av.y; As[lk + 2][lr] = av.z; As[lk + 3][lr] = av.w;
        Bs[lk + 0][lr] = bv.x; Bs[lk + 1][lr] = bv.y; Bs[lk + 2][lr] = bv.z; Bs[lk + 3][lr] = bv.w;
        __syncthreads();
#pragma unroll
        for (int kk = 0; kk < 16; kk++) {
            float4 a = *(const float4*)&As[kk][ty * 4];
            float4 b = *(const float4*)&Bs[kk][tx * 4];
            acc[0][0] += a.x * b.x; acc[0][1] += a.x * b.y; acc[0][2] += a.x * b.z; acc[0][3] += a.x * b.w;
            acc[1][0] += a.y * b.x; acc[1][1] += a.y * b.y; acc[1][2] += a.y * b.z; acc[1][3] += a.y * b.w;
            acc[2][0] += a.z * b.x; acc[2][1] += a.z * b.y; acc[2][2] += a.z * b.z; acc[2][3] += a.z * b.w;
            acc[3][0] += a.w * b.x; acc[3][1] += a.w * b.y; acc[3][2] += a.w * b.z; acc[3][3] += a.w * b.w;
        }
        __syncthreads();
    }
#pragma unroll
    for (int i = 0; i < 4; i++) {
        *(float4*)(C + (size_t)(row0 + ty * 4 + i) * N + col0 + tx * 4) =
            make_float4(acc[i][0], acc[i][1], acc[i][2], acc[i][3]);
    }
}

// ---------------- 6) flash attention: 64-query x 64-key tiles, HD=64 ----------------
#define AW 68
__global__ void attn_kernel() {
    extern __shared__ float sm[];
    float* Qst = sm;                 // [64 d][AW]  (d-major, transposed Q tile)
    float* KP  = sm + 64 * AW;       // K tile d-major, then reused as P [key][AW]
    float* Vs  = sm + 2 * 64 * AW;   // [64 s][64 d] natural
    int b = blockIdx.y >> 4, h = blockIdx.y & 15;
    int q0 = blockIdx.x * 64;
    int tid = threadIdx.x, ty = tid >> 4, tx = tid & 15;
    int lr = tid >> 2;
    int lc = (tid & 3) * 16;
    const float* Qb = g_Q + ((size_t)b * Lc + q0) * Dc + h * HDc;
    const float* Kb = g_K + (size_t)b * Sc * Dc + h * HDc;
    const float* Vb = g_V + (size_t)b * Sc * Dc + h * HDc;
#pragma unroll
    for (int j = 0; j < 4; j++) {
        int d = lc + j * 4;
        float4 v = *(const float4*)(Qb + (size_t)lr * Dc + d);
        Qst[(d + 0) * AW + lr] = v.x; Qst[(d + 1) * AW + lr] = v.y;
        Qst[(d + 2) * AW + lr] = v.z; Qst[(d + 3) * AW + lr] = v.w;
    }
    float m[4], l[4], o[4][4];
#pragma unroll
    for (int i = 0; i < 4; i++) {
        m[i] = -1e30f; l[i] = 0.f;
#pragma unroll
        for (int j = 0; j < 4; j++) o[i][j] = 0.f;
    }
    for (int s0 = 0; s0 < Sc; s0 += 64) {
        __syncthreads();
#pragma unroll
        for (int j = 0; j < 4; j++) {
            int d = lc + j * 4;
            float4 kv = *(const float4*)(Kb + (size_t)(s0 + lr) * Dc + d);
            KP[(d + 0) * AW + lr] = kv.x; KP[(d + 1) * AW + lr] = kv.y;
            KP[(d + 2) * AW + lr] = kv.z; KP[(d + 3) * AW + lr] = kv.w;
            float4 vv = *(const float4*)(Vb + (size_t)(s0 + lr) * Dc + d);
            *(float4*)(Vs + lr * 64 + d) = vv;
        }
        __syncthreads();
        float p[4][4] = {};
#pragma unroll 16
        for (int d = 0; d < 64; d++) {
            float4 a = *(const float4*)(Qst + d * AW + ty * 4);
            float4 bb = *(const float4*)(KP + d * AW + tx * 4);
            p[0][0] += a.x * bb.x; p[0][1] += a.x * bb.y; p[0][2] += a.x * bb.z; p[0][3] += a.x * bb.w;
            p[1][0] += a.y * bb.x; p[1][1] += a.y * bb.y; p[1][2] += a.y * bb.z; p[1][3] += a.y * bb.w;
            p[2][0] += a.z * bb.x; p[2][1] += a.z * bb.y; p[2][2] += a.z * bb.z; p[2][3] += a.z * bb.w;
            p[3][0] += a.w * bb.x; p[3][1] += a.w * bb.y; p[3][2] += a.w * bb.z; p[3][3] += a.w * bb.w;
        }
#pragma unroll
        for (int i = 0; i < 4; i++) {
#pragma unroll
            for (int j = 0; j < 4; j++) p[i][j] *= 0.125f;  // 1/sqrt(64)
            float rmax = fmaxf(fmaxf(p[i][0], p[i][1]), fmaxf(p[i][2], p[i][3]));
#pragma unroll
            for (int off = 1; off < 16; off <<= 1)
                rmax = fmaxf(rmax, __shfl_xor_sync(0xffffffffu, rmax, off));
            float mn = fmaxf(m[i], rmax);
            float al = __expf(m[i] - mn);
            float rs = 0.f;
#pragma unroll
            for (int j = 0; j < 4; j++) { p[i][j] = __expf(p[i][j] - mn); rs += p[i][j]; }
#pragma unroll
            for (int off = 1; off < 16; off <<= 1)
                rs += __shfl_xor_sync(0xffffffffu, rs, off);
            l[i] = l[i] * al + rs;
            m[i] = mn;
#pragma unroll
            for (int j = 0; j < 4; j++) o[i][j] *= al;
        }
        __syncthreads();
#pragma unroll
        for (int j = 0; j < 4; j++)
#pragma unroll
            for (int i = 0; i < 4; i++)
                KP[(tx * 4 + j) * AW + ty * 4 + i] = p[i][j];
        __syncthreads();
#pragma unroll 16
        for (int kk = 0; kk < 64; kk++) {
            float4 a = *(const float4*)(KP + kk * AW + ty * 4);
            float4 bb = *(const float4*)(Vs + kk * 64 + tx * 4);
            o[0][0] += a.x * bb.x; o[0][1] += a.x * bb.y; o[0][2] += a.x * bb.z; o[0][3] += a.x * bb.w;
            o[1][0] += a.y * bb.x; o[1][1] += a.y * bb.y; o[1][2] += a.y * bb.z; o[1][3] += a.y * bb.w;
            o[2][0] += a.z * bb.x; o[2][1] += a.z * bb.y; o[2][2] += a.z * bb.z; o[2][3] += a.z * bb.w;
            o[3][0] += a.w * bb.x; o[3][1] += a.w * bb.y; o[3][2] += a.w * bb.z; o[3][3] += a.w * bb.w;
        }
    }
    float* Ob = g_ao + ((size_t)b * Lc + q0) * Dc + h * HDc;
#pragma unroll
    for (int i = 0; i < 4; i++) {
        float inv = 1.0f / l[i];
        *(float4*)(Ob + (size_t)(ty * 4 + i) * Dc + tx * 4) =
            make_float4(o[i][0] * inv, o[i][1] * inv, o[i][2] * inv, o[i][3] * inv);
    }
}

// ---------------- launch ----------------
extern "C" void kernel_launch(void* const* d_in, const int* in_sizes, int n_in,
                              void* d_out, int out_size) {
    const float* x_q  = (const float*)d_in[0];
    const int*   xidx = (const int*)d_in[1];
    const float* E    = (const float*)d_in[2];
    const float* rhos = (const float*)d_in[3];
    const float* Cs   = (const float*)d_in[4];
    const float* Wq   = (const float*)d_in[5];
    const float* Wk   = (const float*)d_in[6];
    const float* Wv   = (const float*)d_in[7];
    const float* Wo   = (const float*)d_in[8];
    const float* Wpe  = (const float*)d_in[9];
    const float* lnkg = (const float*)d_in[10];
    const float* lnkb = (const float*)d_in[11];
    const float* lnqg = (const float*)d_in[12];
    const float* lnqb = (const float*)d_in[13];
    float* out = (float*)d_out;

    float *p_mem, *p_ek, *p_ev, *p_xh, *p_Q, *p_ao;
    cudaGetSymbolAddress((void**)&p_mem, g_mem);
    cudaGetSymbolAddress((void**)&p_ek, g_ek);
    cudaGetSymbolAddress((void**)&p_ev, g_ev);
    cudaGetSymbolAddress((void**)&p_xh, g_xh);
    cudaGetSymbolAddress((void**)&p_Q, g_Q);
    cudaGetSymbolAddress((void**)&p_ao, g_ao);

    // KV side
    ln_rows_kernel<<<NSLOTc, 256>>>(E, lnkg, lnkb, p_mem);
    gemm_abt_kernel<<<dim3(Dc / 64, NSLOTc / 64), 256>>>(p_mem, Wk, p_ek, NSLOTc, Dc, Dc);
    gemm_abt_kernel<<<dim3(Dc / 64, NSLOTc / 64), 256>>>(p_mem, Wv, p_ev, NSLOTc, Dc, Dc);
    gatekv_kernel<<<Sc, 256>>>(rhos, Wpe);
    gather_kernel<<<Bc * Sc, 256>>>(xidx);

    // Q side
    gateq_ln_kernel<<<Bc * Lc, 256>>>(x_q, Cs, Wpe, lnqg, lnqb);
    gemm_abt_kernel<<<dim3(Dc / 64, (Bc * Lc) / 64), 256>>>(p_xh, Wq, p_Q, Bc * Lc, Dc, Dc);

    // Attention
    const int attn_smem = (2 * 64 * AW + 64 * 64) * (int)sizeof(float);  // 51200 B
    cudaFuncSetAttribute(attn_kernel, cudaFuncAttributeMaxDynamicSharedMemorySize, attn_smem);
    attn_kernel<<<dim3(Lc / 64, Bc * Hc), 256, attn_smem>>>();

    // Output projection
    gemm_abt_kernel<<<dim3(Dc / 64, (Bc * Lc) / 64), 256>>>(p_ao, Wo, out, Bc * Lc, Dc, Dc);
}